// round 13
// baseline (speedup 1.0000x reference)
#include <cuda_runtime.h>
#include <cuda_fp16.h>
#include <cstdint>

// ---------------- problem constants ----------------
#define CCH   200               // channels
#define NC8   25                // uint4 (8-half) chunks per position
#define D3    16
#define H3    60
#define W3    80
#define P3    (D3*H3*W3)        // 76800
#define H2    120
#define W2    160
#define P2    (H2*W2)           // 19200
#define XDIM  60
#define YDIM  36
#define ZDIM  60
#define NVOX  (XDIM*YDIM*ZDIM)  // 129600
#define NB    2
#define VPB   10                // voxels per block
#define ZCH   (ZDIM/VPB)        // 6

#define T3TILES (P3/32)         // 2400
#define T2TILES (P2/32)         // 600
#define NTT     ((T3TILES+T2TILES)*7)   // 21000 transpose blocks (flat pt,ct)
#define NSB     (XDIM*YDIM*ZCH)         // 12960 sample blocks per batch
// interleave groups: gcd(21000,12960)=120 -> 175 T + 108 S per group
#define GRP_T   175
#define GRP_S   108
#define GRP_SZ  (GRP_T+GRP_S)   // 283

// channel-last fp16 scratch: s3[b][pos][c], s2[b][pos][c]
__device__ __align__(16) __half g_s3[NB * P3 * CCH];   // 61.4 MB
__device__ __align__(16) __half g_s2[NB * P2 * CCH];   // 15.4 MB

// ---------------- shared-memory union ----------------
struct SampleSh {
    int   off[VPB][12];
    float w[VPB][12];
    float st[VPB][204];
};
struct TransSh { float tile[32][33]; };
union ShU { SampleSh s; TransSh t; };

// ---------------- transpose block body (one 32x32 tile, one batch) --------
__device__ __forceinline__ void transpose_body(
    TransSh& sh, int flat, int batch,
    const float* __restrict__ a3, const float* __restrict__ b3,
    const float* __restrict__ a2, const float* __restrict__ b2)
{
    int pt = flat % (T3TILES + T2TILES);
    const int ct = flat / (T3TILES + T2TILES);   // 0..6
    const int tid = threadIdx.x;
    const int tx = tid & 31, ty = tid >> 5;      // 32 x 8

    const float *ab, *bb;
    __half* db;
    int P;
    if (pt < T3TILES) {
        P  = P3;
        ab = a3 + (size_t)batch * CCH * P3;
        bb = b3 + (size_t)batch * CCH * P3;
        db = g_s3 + (size_t)batch * P3 * CCH;
    } else {
        pt -= T3TILES;
        P  = P2;
        ab = a2 + (size_t)batch * CCH * P2;
        bb = b2 + (size_t)batch * CCH * P2;
        db = g_s2 + (size_t)batch * P2 * CCH;
    }

    const int p0 = pt * 32, c0 = ct * 32;
    #pragma unroll
    for (int i = 0; i < 32; i += 8) {
        int c = c0 + ty + i;
        int p = p0 + tx;
        if (c < CCH)
            sh.tile[ty + i][tx] = ab[(size_t)c * P + p] + bb[(size_t)c * P + p];
    }
    __syncthreads();
    #pragma unroll
    for (int i = 0; i < 32; i += 8) {
        int p = p0 + ty + i;
        int c = c0 + tx;
        if (c < CCH)
            db[(size_t)p * CCH + c] = __float2half_rn(sh.tile[tx][ty + i]);
    }
}

// ---------------- sample block body (10 voxels, one batch) ----------------
__device__ __forceinline__ void sample_body(
    SampleSh& sh, int sid, int b,
    const float* __restrict__ pp, float* __restrict__ out)
{
    const int zc  = sid % ZCH;
    int rest      = sid / ZCH;
    const int y   = rest % YDIM; rest /= YDIM;
    const int x   = rest;                // 0..59
    const int z0  = zc * VPB;
    const int tid = threadIdx.x;

    // Phase A: tap setup
    if (tid < VPB * 12) {
        const int q = tid / 12;
        const int t = tid % 12;          // 0..7 = 3D, 8..11 = 2D
        const int z = z0 + q;
        const int v = x * (ZDIM * YDIM) + z * YDIM + y;
        const float* g = pp + ((size_t)b * NVOX + v) * 3;
        const float px = __ldg(g + 0), py = __ldg(g + 1);

        int offset; float weight;
        if (t < 8) {
            const float pz = __ldg(g + 2);
            const float gx = (px + 1.f) * 0.5f * (W3 - 1);
            const float gy = (py + 1.f) * 0.5f * (H3 - 1);
            const float gz = (pz + 1.f) * 0.5f * (D3 - 1);
            const float fx = floorf(gx), fy = floorf(gy), fz = floorf(gz);
            const float wx = gx - fx, wy = gy - fy, wz = gz - fz;
            const int dx = t & 1, dy = (t >> 1) & 1, dz = (t >> 2) & 1;
            const int xi = (int)fx + dx, yi = (int)fy + dy, zi = (int)fz + dz;
            const bool valid = (xi >= 0) & (xi < W3) & (yi >= 0) & (yi < H3) &
                               (zi >= 0) & (zi < D3);
            const int xc = min(max(xi, 0), W3 - 1);
            const int yc = min(max(yi, 0), H3 - 1);
            const int zcv = min(max(zi, 0), D3 - 1);
            const int pos = (zcv * H3 + yc) * W3 + xc;
            offset = b * (P3 * NC8) + pos * NC8;
            float w = (dx ? wx : 1.f - wx) * (dy ? wy : 1.f - wy) *
                      (dz ? wz : 1.f - wz);
            weight = valid ? w : 0.f;
        } else {
            const float gx = (px + 1.f) * 0.5f * (W2 - 1);
            const float gy = (py + 1.f) * 0.5f * (H2 - 1);
            const float fx = floorf(gx), fy = floorf(gy);
            const float wx = gx - fx, wy = gy - fy;
            const int tt = t - 8;
            const int dx = tt & 1, dy = (tt >> 1) & 1;
            const int xi = (int)fx + dx, yi = (int)fy + dy;
            const bool valid = (xi >= 0) & (xi < W2) & (yi >= 0) & (yi < H2);
            const int xc = min(max(xi, 0), W2 - 1);
            const int yc = min(max(yi, 0), H2 - 1);
            const int pos = yc * W2 + xc;
            offset = b * (P2 * NC8) + pos * NC8;
            float w = (dx ? wx : 1.f - wx) * (dy ? wy : 1.f - wy);
            weight = valid ? w : 0.f;
        }
        sh.off[q][t] = offset;
        sh.w[q][t]   = weight;
    }
    __syncthreads();

    // Phase B: gather (fp16 taps, fp32 accum)
    if (tid < VPB * NC8) {               // 250 active
        const int q  = tid / NC8;
        const int cc = tid % NC8;
        const uint4* s3 = (const uint4*)g_s3;
        const uint4* s2 = (const uint4*)g_s2;

        float ax = 0.f, ay = 0.f, az = 0.f, aw = 0.f;
        float bx = 0.f, by = 0.f, bz = 0.f, bw = 0.f;
        #pragma unroll
        for (int t = 0; t < 12; t++) {
            const uint4 vv = (t < 8) ? s3[sh.off[q][t] + cc]
                                     : s2[sh.off[q][t] + cc];
            const float w = sh.w[q][t];
            const __half2* h = (const __half2*)&vv;
            const float2 f0 = __half22float2(h[0]);
            const float2 f1 = __half22float2(h[1]);
            const float2 f2 = __half22float2(h[2]);
            const float2 f3 = __half22float2(h[3]);
            ax += w * f0.x; ay += w * f0.y;
            az += w * f1.x; aw += w * f1.y;
            bx += w * f2.x; by += w * f2.y;
            bz += w * f3.x; bw += w * f3.y;
        }
        *(float4*)&sh.st[q][cc * 8]     = make_float4(ax, ay, az, aw);
        *(float4*)&sh.st[q][cc * 8 + 4] = make_float4(bx, by, bz, bw);
    }
    __syncthreads();

    // Phase C: coalesced write-out: out[b][c][x][y][z]
    float* ob = out + (size_t)b * CCH * NVOX +
                ((size_t)x * YDIM + y) * ZDIM + z0;
    for (int idx = tid; idx < CCH * (VPB / 2); idx += 256) {
        const int c  = idx / (VPB / 2);
        const int zp = idx % (VPB / 2);
        float2 v = make_float2(sh.st[2 * zp][c], sh.st[2 * zp + 1][c]);
        __stcs((float2*)(ob + (size_t)c * NVOX + 2 * zp), v);
    }
}

// ---------------- stage 1: transpose batch 0 ----------------
__global__ void __launch_bounds__(256) t0_kernel(
    const float* __restrict__ a3, const float* __restrict__ b3,
    const float* __restrict__ a2, const float* __restrict__ b2)
{
    __shared__ TransSh sh;
    transpose_body(sh, blockIdx.x, 0, a3, b3, a2, b2);
}

// ---------------- stage 2: interleaved T(b1) + S(b0) ----------------
__global__ void __launch_bounds__(256) mid_kernel(
    const float* __restrict__ a3, const float* __restrict__ b3,
    const float* __restrict__ a2, const float* __restrict__ b2,
    const float* __restrict__ pp, float* __restrict__ out)
{
    __shared__ ShU sh;
    const int bid = blockIdx.x;
    const int grp = bid / GRP_SZ;
    const int pos = bid % GRP_SZ;
    if (pos < GRP_T) {
        transpose_body(sh.t, grp * GRP_T + pos, 1, a3, b3, a2, b2);
    } else {
        sample_body(sh.s, grp * GRP_S + (pos - GRP_T), 0, pp, out);
    }
}

// ---------------- stage 3: sample batch 1 ----------------
__global__ void __launch_bounds__(256) s1_kernel(
    const float* __restrict__ pp, float* __restrict__ out)
{
    __shared__ SampleSh sh;
    sample_body(sh, blockIdx.x, 1, pp, out);
}

// ---------------- launch ----------------
extern "C" void kernel_launch(void* const* d_in, const int* in_sizes, int n_in,
                              void* d_out, int out_size)
{
    const float* x3a = (const float*)d_in[0];
    const float* x3b = (const float*)d_in[1];
    const float* x2a = (const float*)d_in[2];
    const float* x2b = (const float*)d_in[3];
    const float* pp  = (const float*)d_in[4];
    float* out = (float*)d_out;

    // stage 1: T(b0)
    t0_kernel<<<NTT, 256>>>(x3a, x3b, x2a, x2b);
    // stage 2: T(b1) interleaved with S(b0)  (120 groups x 283 blocks)
    mid_kernel<<<NTT + NSB, 256>>>(x3a, x3b, x2a, x2b, pp, out);
    // stage 3: S(b1)
    s1_kernel<<<NSB, 256>>>(pp, out);
}

// round 14
// speedup vs baseline: 1.1653x; 1.1653x over previous
#include <cuda_runtime.h>
#include <cuda_fp16.h>
#include <cstdint>

// ---------------- problem constants ----------------
#define CCH   200               // channels
#define NC8   25                // uint4 (8-half) chunks per position
#define D3    16
#define H3    60
#define W3    80
#define P3    (D3*H3*W3)        // 76800
#define H2    120
#define W2    160
#define P2    (H2*W2)           // 19200
#define XDIM  60
#define YDIM  36
#define ZDIM  60
#define NVOX  (XDIM*YDIM*ZDIM)  // 129600
#define NB    2
#define VPB   12                // voxels per block
#define ZCH   (ZDIM/VPB)        // 5

#define T3TILES (P3/32)         // 2400
#define T2TILES (P2/32)         // 600

// channel-last fp16 scratch: s3[b][pos][c], s2[b][pos][c]
__device__ __align__(16) __half g_s3[NB * P3 * CCH];   // 61.4 MB
__device__ __align__(16) __half g_s2[NB * P2 * CCH];   // 15.4 MB

// ---------------- pass 1: fused add + transpose (C,P)->(P,C), fp32->fp16 ---
__global__ void transpose_add_kernel(const float* __restrict__ a3,
                                     const float* __restrict__ b3,
                                     const float* __restrict__ a2,
                                     const float* __restrict__ b2,
                                     __half* __restrict__ d3,
                                     __half* __restrict__ d2)
{
    __shared__ float tile[32][33];
    int pt = blockIdx.x;
    const int ct = blockIdx.y;
    const int batch = blockIdx.z;

    const float *ab, *bb;
    __half* db;
    int P;
    if (pt < T3TILES) {
        P  = P3;
        ab = a3 + (size_t)batch * CCH * P3;
        bb = b3 + (size_t)batch * CCH * P3;
        db = d3 + (size_t)batch * P3 * CCH;
    } else {
        pt -= T3TILES;
        P  = P2;
        ab = a2 + (size_t)batch * CCH * P2;
        bb = b2 + (size_t)batch * CCH * P2;
        db = d2 + (size_t)batch * P2 * CCH;
    }

    const int p0 = pt * 32, c0 = ct * 32;
    const int tx = threadIdx.x, ty = threadIdx.y;   // 32 x 8

    #pragma unroll
    for (int i = 0; i < 32; i += 8) {
        int c = c0 + ty + i;
        int p = p0 + tx;
        if (c < CCH)
            tile[ty + i][tx] = __ldcs(&ab[(size_t)c * P + p]) +
                               __ldcs(&bb[(size_t)c * P + p]);
    }
    __syncthreads();
    #pragma unroll
    for (int i = 0; i < 32; i += 8) {
        int p = p0 + ty + i;
        int c = c0 + tx;
        if (c < CCH)
            db[(size_t)p * CCH + c] = __float2half_rn(tile[tx][ty + i]);
    }
}

// ---------------- pass 2: 12 voxels per 320-thread block ----------------
__global__ void __launch_bounds__(320) sample_kernel(const float* __restrict__ pp,
                                                     float* __restrict__ out)
{
    __shared__ int   sm_off[VPB][12];    // uint4-index incl. batch base
    __shared__ float sm_w[VPB][12];
    __shared__ float st[VPB][204];       // staged results

    const int bid = blockIdx.x;
    const int zc  = bid % ZCH;
    int rest      = bid / ZCH;
    const int y   = rest % YDIM; rest /= YDIM;
    const int x   = rest % XDIM;
    const int b   = rest / XDIM;
    const int z0  = zc * VPB;
    const int tid = threadIdx.x;

    // ---------- Phase A: tap setup (one thread per voxel-tap) ----------
    if (tid < VPB * 12) {                // 144 active
        const int q = tid / 12;
        const int t = tid % 12;          // 0..7 = 3D, 8..11 = 2D
        const int z = z0 + q;
        const int v = x * (ZDIM * YDIM) + z * YDIM + y;
        const float* g = pp + ((size_t)b * NVOX + v) * 3;
        const float px = __ldg(g + 0), py = __ldg(g + 1);

        int offset; float weight;
        if (t < 8) {
            const float pz = __ldg(g + 2);
            const float gx = (px + 1.f) * 0.5f * (W3 - 1);
            const float gy = (py + 1.f) * 0.5f * (H3 - 1);
            const float gz = (pz + 1.f) * 0.5f * (D3 - 1);
            const float fx = floorf(gx), fy = floorf(gy), fz = floorf(gz);
            const float wx = gx - fx, wy = gy - fy, wz = gz - fz;
            const int dx = t & 1, dy = (t >> 1) & 1, dz = (t >> 2) & 1;
            const int xi = (int)fx + dx, yi = (int)fy + dy, zi = (int)fz + dz;
            const bool valid = (xi >= 0) & (xi < W3) & (yi >= 0) & (yi < H3) &
                               (zi >= 0) & (zi < D3);
            const int xc = min(max(xi, 0), W3 - 1);
            const int yc = min(max(yi, 0), H3 - 1);
            const int zcv = min(max(zi, 0), D3 - 1);
            const int pos = (zcv * H3 + yc) * W3 + xc;
            offset = b * (P3 * NC8) + pos * NC8;
            float w = (dx ? wx : 1.f - wx) * (dy ? wy : 1.f - wy) *
                      (dz ? wz : 1.f - wz);
            weight = valid ? w : 0.f;
        } else {
            const float gx = (px + 1.f) * 0.5f * (W2 - 1);
            const float gy = (py + 1.f) * 0.5f * (H2 - 1);
            const float fx = floorf(gx), fy = floorf(gy);
            const float wx = gx - fx, wy = gy - fy;
            const int tt = t - 8;
            const int dx = tt & 1, dy = (tt >> 1) & 1;
            const int xi = (int)fx + dx, yi = (int)fy + dy;
            const bool valid = (xi >= 0) & (xi < W2) & (yi >= 0) & (yi < H2);
            const int xc = min(max(xi, 0), W2 - 1);
            const int yc = min(max(yi, 0), H2 - 1);
            const int pos = yc * W2 + xc;
            offset = b * (P2 * NC8) + pos * NC8;
            float w = (dx ? wx : 1.f - wx) * (dy ? wy : 1.f - wy);
            weight = valid ? w : 0.f;
        }
        sm_off[q][t] = offset;
        sm_w[q][t]   = weight;
    }
    __syncthreads();

    // ---------- Phase B: gather (fp16 taps, fp32 accum) ----------
    if (tid < VPB * NC8) {               // 300 active
        const int q  = tid / NC8;
        const int cc = tid % NC8;
        const uint4* s3 = (const uint4*)g_s3;
        const uint4* s2 = (const uint4*)g_s2;

        float ax = 0.f, ay = 0.f, az = 0.f, aw = 0.f;
        float bx = 0.f, by = 0.f, bz = 0.f, bw = 0.f;
        #pragma unroll
        for (int t = 0; t < 12; t++) {
            const uint4 vv = (t < 8) ? s3[sm_off[q][t] + cc]
                                     : s2[sm_off[q][t] + cc];
            const float w = sm_w[q][t];
            const __half2* h = (const __half2*)&vv;
            const float2 f0 = __half22float2(h[0]);
            const float2 f1 = __half22float2(h[1]);
            const float2 f2 = __half22float2(h[2]);
            const float2 f3 = __half22float2(h[3]);
            ax += w * f0.x; ay += w * f0.y;
            az += w * f1.x; aw += w * f1.y;
            bx += w * f2.x; by += w * f2.y;
            bz += w * f3.x; bw += w * f3.y;
        }
        *(float4*)&st[q][cc * 8]     = make_float4(ax, ay, az, aw);
        *(float4*)&st[q][cc * 8 + 4] = make_float4(bx, by, bz, bw);
    }
    __syncthreads();

    // ---------- Phase C: coalesced write-out: out[b][c][x][y][z] ----------
    float* ob = out + (size_t)b * CCH * NVOX +
                ((size_t)x * YDIM + y) * ZDIM + z0;
    for (int idx = tid; idx < CCH * (VPB / 2); idx += 320) {
        const int c  = idx / (VPB / 2);
        const int zp = idx % (VPB / 2);
        float2 v = make_float2(st[2 * zp][c], st[2 * zp + 1][c]);
        __stcs((float2*)(ob + (size_t)c * NVOX + 2 * zp), v);
    }
}

// ---------------- launch ----------------
extern "C" void kernel_launch(void* const* d_in, const int* in_sizes, int n_in,
                              void* d_out, int out_size)
{
    const float* x3a = (const float*)d_in[0];
    const float* x3b = (const float*)d_in[1];
    const float* x2a = (const float*)d_in[2];
    const float* x2b = (const float*)d_in[3];
    const float* pp  = (const float*)d_in[4];
    float* out = (float*)d_out;

    __half* s3ptr = nullptr;
    __half* s2ptr = nullptr;
    cudaGetSymbolAddress((void**)&s3ptr, g_s3);
    cudaGetSymbolAddress((void**)&s2ptr, g_s2);

    // pass 1: fused fold + transpose (3D + 2D, both batches)
    {
        dim3 blk(32, 8);
        dim3 grd(T3TILES + T2TILES, (CCH + 31) / 32, NB);  // 3000 x 7 x 2
        transpose_add_kernel<<<grd, blk>>>(x3a, x3b, x2a, x2b, s3ptr, s2ptr);
    }

    // pass 2: 12-voxel blocks
    {
        const int nblocks = NB * XDIM * YDIM * ZCH;  // 21600
        sample_kernel<<<nblocks, 320>>>(pp, out);
    }
}